// round 2
// baseline (speedup 1.0000x reference)
#include <cuda_runtime.h>
#include <cstdint>

#define N_NODES 50000
#define N_EDGES 800000
#define D 128

// Scratch for projected features h = x @ W^T + b (immutable during scatter).
__device__ float g_h[(size_t)N_NODES * D];
// Edge-index dtype flag: 1 if int64, 0 if int32. Written by detect kernel.
__device__ int g_ei_is64;

// ---------------------------------------------------------------------------
// Kernel 0: detect edge_index dtype. If the buffer really holds int64 values
// in [0, N_NODES), every int64 word is small. If it holds int32 pairs, the
// reinterpreted int64 is lo + hi*2^32 which is >= 2^32 whenever the odd-slot
// value is nonzero (probability ~1 for random indices). Sample 64 values.
// ---------------------------------------------------------------------------
__global__ void detect_ei_dtype_kernel(const long long* __restrict__ ei) {
    if (threadIdx.x == 0) {
        int is64 = 1;
        for (int i = 0; i < 64; i++) {
            long long v = ei[i];
            if (v < 0 || v >= N_NODES) { is64 = 0; break; }
        }
        g_ei_is64 = is64;
    }
}

// ---------------------------------------------------------------------------
// Kernel 1: tiled SGEMM. h[r][j] = sum_k x[r][k] * W[j][k] + b[j]
// Writes h to g_h and also initializes out = h (residual term).
// ---------------------------------------------------------------------------
#define BM 128
#define BK 32
#define SPAD 132

__global__ __launch_bounds__(256, 2)
void gemm_bias_kernel(const float* __restrict__ x,
                      const float* __restrict__ W,
                      const float* __restrict__ b,
                      float* __restrict__ out) {
    __shared__ float xs[BK][SPAD];  // xs[kk][r_local]
    __shared__ float ws[BK][SPAD];  // ws[kk][j]

    const int tid  = threadIdx.x;
    const int tx   = tid & 15;
    const int ty   = tid >> 4;
    const int row0 = blockIdx.x * BM;

    float acc[8][8];
#pragma unroll
    for (int i = 0; i < 8; i++)
#pragma unroll
        for (int j = 0; j < 8; j++) acc[i][j] = 0.0f;

    for (int k0 = 0; k0 < D; k0 += BK) {
        for (int idx = tid; idx < D * BK; idx += 256) {
            int j  = idx >> 5;
            int kk = idx & 31;
            ws[kk][j] = W[j * D + k0 + kk];
        }
        for (int idx = tid; idx < BM * BK; idx += 256) {
            int r  = idx >> 5;
            int kk = idx & 31;
            int gr = row0 + r;
            xs[kk][r] = (gr < N_NODES) ? x[(size_t)gr * D + k0 + kk] : 0.0f;
        }
        __syncthreads();

#pragma unroll 8
        for (int kk = 0; kk < BK; ++kk) {
            float a[8], w[8];
#pragma unroll
            for (int i = 0; i < 8; i++) a[i] = xs[kk][ty * 8 + i];
#pragma unroll
            for (int j = 0; j < 8; j++) w[j] = ws[kk][tx * 8 + j];
#pragma unroll
            for (int i = 0; i < 8; i++)
#pragma unroll
                for (int j = 0; j < 8; j++) acc[i][j] += a[i] * w[j];
        }
        __syncthreads();
    }

    float bias[8];
#pragma unroll
    for (int j = 0; j < 8; j++) bias[j] = b[tx * 8 + j];

#pragma unroll
    for (int i = 0; i < 8; i++) {
        int r = row0 + ty * 8 + i;
        if (r < N_NODES) {
            size_t base = (size_t)r * D + tx * 8;
#pragma unroll
            for (int j = 0; j < 8; j++) {
                float v = acc[i][j] + bias[j];
                g_h[base + j] = v;
                out[base + j] = v;
            }
        }
    }
}

// ---------------------------------------------------------------------------
// Kernel 2: edge gather + scatter-add. One warp per edge; each lane owns one
// float4. out[row] += h[col] via red.global.add.v4.f32.
// Handles both int32 and int64 edge_index via g_ei_is64.
// ---------------------------------------------------------------------------
__global__ __launch_bounds__(256)
void edge_scatter_kernel(const void* __restrict__ ei_raw,
                         float* __restrict__ out) {
    const int edge = (blockIdx.x * blockDim.x + threadIdx.x) >> 5;
    const int lane = threadIdx.x & 31;
    if (edge >= N_EDGES) return;

    long long row, col;
    if (g_ei_is64) {
        const long long* ei = (const long long*)ei_raw;
        row = ei[edge];
        col = ei[N_EDGES + edge];
    } else {
        const int* ei = (const int*)ei_raw;
        row = ei[edge];
        col = ei[N_EDGES + edge];
    }
    // Safety clamp: never generate an OOB address even if indices are weird.
    if (row < 0 || row >= N_NODES || col < 0 || col >= N_NODES) return;

    const float4* __restrict__ src =
        reinterpret_cast<const float4*>(g_h + (size_t)col * D);
    float4 v = src[lane];

    float* dst = out + (size_t)row * D + (size_t)lane * 4;
    asm volatile("red.global.add.v4.f32 [%0], {%1, %2, %3, %4};"
                 :: "l"(dst), "f"(v.x), "f"(v.y), "f"(v.z), "f"(v.w)
                 : "memory");
}

// ---------------------------------------------------------------------------
extern "C" void kernel_launch(void* const* d_in, const int* in_sizes, int n_in,
                              void* d_out, int out_size) {
    // Identify inputs by element count (all distinct) — immune to ordering.
    const float* x = nullptr; const void* ei = nullptr;
    const float* W = nullptr; const float* b = nullptr;
    for (int i = 0; i < n_in; i++) {
        switch (in_sizes[i]) {
            case N_NODES * D:   x  = (const float*)d_in[i]; break;  // 6,400,000
            case 2 * N_EDGES:   ei = d_in[i];               break;  // 1,600,000
            case D * D:         W  = (const float*)d_in[i]; break;  // 16,384
            case D:             b  = (const float*)d_in[i]; break;  // 128
        }
    }
    float* out = (float*)d_out;

    detect_ei_dtype_kernel<<<1, 32>>>((const long long*)ei);

    const int gemm_blocks = (N_NODES + BM - 1) / BM;
    gemm_bias_kernel<<<gemm_blocks, 256>>>(x, W, b, out);

    const int edges_per_block = 256 / 32;
    const int scatter_blocks = (N_EDGES + edges_per_block - 1) / edges_per_block;
    edge_scatter_kernel<<<scatter_blocks, 256>>>(ei, out);
}

// round 4
// speedup vs baseline: 1.4364x; 1.4364x over previous
#include <cuda_runtime.h>
#include <cuda_bf16.h>
#include <cstdint>

#define N_NODES 50000
#define N_EDGES 800000
#define D 128

// Scratch for projected features h = x @ W^T + b (immutable during scatter).
__device__ float g_h[(size_t)N_NODES * D];

// ---------------------------------------------------------------------------
// Kernel 1: tensor-core GEMM via mma.sync m16n8k16 bf16, 3-pass fp32 split.
// h[r][n] = sum_k x[r][k] * W[n][k] + b[n]. Writes g_h and out (= h).
// CTA: 256 threads, one 128(M) x 128(N) tile, full K=128.
// ---------------------------------------------------------------------------
#define AS 136  // padded bf16 row stride (136*2 = 272 B; 272/4 mod 32 = 4 -> conflict-free)

// dynamic smem layout (bf16 elements):
//  A_hi[128][136], A_lo[128][136], B_hi[128][136], B_lo[128][136], bias f32[128]
#define OFF_A_HI 0
#define OFF_A_LO (128 * AS)
#define OFF_B_HI (2 * 128 * AS)
#define OFF_B_LO (3 * 128 * AS)
#define SMEM_BF16_ELEMS (4 * 128 * AS)
#define SM_TOTAL (SMEM_BF16_ELEMS * 2 + 512)

__device__ __forceinline__ void mma16816(float* c, const uint32_t* a, const uint32_t* bq) {
    asm volatile(
        "mma.sync.aligned.m16n8k16.row.col.f32.bf16.bf16.f32 "
        "{%0,%1,%2,%3}, {%4,%5,%6,%7}, {%8,%9}, {%0,%1,%2,%3};"
        : "+f"(c[0]), "+f"(c[1]), "+f"(c[2]), "+f"(c[3])
        : "r"(a[0]), "r"(a[1]), "r"(a[2]), "r"(a[3]), "r"(bq[0]), "r"(bq[1]));
}

__device__ __forceinline__ uint2 split_f4(float4 v) {
    __nv_bfloat16 h0 = __float2bfloat16(v.x), h1 = __float2bfloat16(v.y);
    __nv_bfloat16 h2 = __float2bfloat16(v.z), h3 = __float2bfloat16(v.w);
    __nv_bfloat162 a(h0, h1), bb(h2, h3);
    uint2 r;
    r.x = *reinterpret_cast<uint32_t*>(&a);
    r.y = *reinterpret_cast<uint32_t*>(&bb);
    return r;
}
__device__ __forceinline__ uint2 split_f4_lo(float4 v) {
    __nv_bfloat16 h0 = __float2bfloat16(v.x), h1 = __float2bfloat16(v.y);
    __nv_bfloat16 h2 = __float2bfloat16(v.z), h3 = __float2bfloat16(v.w);
    __nv_bfloat16 l0 = __float2bfloat16(v.x - __bfloat162float(h0));
    __nv_bfloat16 l1 = __float2bfloat16(v.y - __bfloat162float(h1));
    __nv_bfloat16 l2 = __float2bfloat16(v.z - __bfloat162float(h2));
    __nv_bfloat16 l3 = __float2bfloat16(v.w - __bfloat162float(h3));
    __nv_bfloat162 a(l0, l1), bb(l2, l3);
    uint2 r;
    r.x = *reinterpret_cast<uint32_t*>(&a);
    r.y = *reinterpret_cast<uint32_t*>(&bb);
    return r;
}

__global__ __launch_bounds__(256, 1)
void gemm_tc_kernel(const float* __restrict__ x,
                    const float* __restrict__ W,
                    const float* __restrict__ b,
                    float* __restrict__ out) {
    extern __shared__ __nv_bfloat16 smem[];
    float* bias_s = reinterpret_cast<float*>(smem + SMEM_BF16_ELEMS);

    const int tid = threadIdx.x;
    const int wid = tid >> 5;
    const int lane = tid & 31;
    const int row0 = blockIdx.x * 128;

    if (tid < D) bias_s[tid] = b[tid];

    // ---- Load + split x tile and W into smem (hi/lo bf16, padded rows) ----
    for (int idx = tid; idx < 4096; idx += 256) {
        int r = idx >> 5;
        int k = (idx & 31) << 2;
        int gr = row0 + r;
        float4 v = (gr < N_NODES)
            ? *reinterpret_cast<const float4*>(x + (size_t)gr * D + k)
            : make_float4(0.f, 0.f, 0.f, 0.f);
        *reinterpret_cast<uint2*>(smem + OFF_A_HI + r * AS + k) = split_f4(v);
        *reinterpret_cast<uint2*>(smem + OFF_A_LO + r * AS + k) = split_f4_lo(v);
    }
    for (int idx = tid; idx < 4096; idx += 256) {
        int r = idx >> 5;
        int k = (idx & 31) << 2;
        float4 v = *reinterpret_cast<const float4*>(W + (size_t)r * D + k);
        *reinterpret_cast<uint2*>(smem + OFF_B_HI + r * AS + k) = split_f4(v);
        *reinterpret_cast<uint2*>(smem + OFF_B_LO + r * AS + k) = split_f4_lo(v);
    }
    __syncthreads();

    // ---- Warp tiling: 4(M) x 2(N) warps, each 32 x 64 ----
    const int m0 = (wid >> 1) * 32;
    const int n0 = (wid & 1) * 64;
    const int qr = lane >> 2;        // 0..7
    const int qc = lane & 3;         // 0..3

    float acc[2][8][4];
#pragma unroll
    for (int i = 0; i < 2; i++)
#pragma unroll
        for (int j = 0; j < 8; j++)
#pragma unroll
            for (int t = 0; t < 4; t++) acc[i][j][t] = 0.0f;

    // 3 passes: A_hi*B_hi, A_hi*B_lo, A_lo*B_hi
    const int a_off[3] = {OFF_A_HI, OFF_A_HI, OFF_A_LO};
    const int b_off[3] = {OFF_B_HI, OFF_B_LO, OFF_B_HI};

#pragma unroll
    for (int pass = 0; pass < 3; pass++) {
        const __nv_bfloat16* A = smem + a_off[pass];
        const __nv_bfloat16* B = smem + b_off[pass];
#pragma unroll
        for (int k0 = 0; k0 < 128; k0 += 16) {
            uint32_t afr[2][4];
#pragma unroll
            for (int mi = 0; mi < 2; mi++) {
                const __nv_bfloat16* base = A + (m0 + mi * 16 + qr) * AS + k0 + qc * 2;
                afr[mi][0] = *reinterpret_cast<const uint32_t*>(base);
                afr[mi][1] = *reinterpret_cast<const uint32_t*>(base + 8 * AS);
                afr[mi][2] = *reinterpret_cast<const uint32_t*>(base + 8);
                afr[mi][3] = *reinterpret_cast<const uint32_t*>(base + 8 * AS + 8);
            }
#pragma unroll
            for (int ni = 0; ni < 8; ni++) {
                const __nv_bfloat16* base = B + (n0 + ni * 8 + qr) * AS + k0 + qc * 2;
                uint32_t bfr[2];
                bfr[0] = *reinterpret_cast<const uint32_t*>(base);
                bfr[1] = *reinterpret_cast<const uint32_t*>(base + 8);
#pragma unroll
                for (int mi = 0; mi < 2; mi++)
                    mma16816(acc[mi][ni], afr[mi], bfr);
            }
        }
    }

    // ---- Epilogue: add bias, write g_h and out ----
#pragma unroll
    for (int mi = 0; mi < 2; mi++) {
        int r_lo = row0 + m0 + mi * 16 + qr;
        int r_hi = r_lo + 8;
#pragma unroll
        for (int ni = 0; ni < 8; ni++) {
            int c = n0 + ni * 8 + qc * 2;
            float2 bv = *reinterpret_cast<const float2*>(bias_s + c);
            if (r_lo < N_NODES) {
                float2 v = make_float2(acc[mi][ni][0] + bv.x, acc[mi][ni][1] + bv.y);
                *reinterpret_cast<float2*>(g_h + (size_t)r_lo * D + c) = v;
                *reinterpret_cast<float2*>(out + (size_t)r_lo * D + c) = v;
            }
            if (r_hi < N_NODES) {
                float2 v = make_float2(acc[mi][ni][2] + bv.x, acc[mi][ni][3] + bv.y);
                *reinterpret_cast<float2*>(g_h + (size_t)r_hi * D + c) = v;
                *reinterpret_cast<float2*>(out + (size_t)r_hi * D + c) = v;
            }
        }
    }
}

// ---------------------------------------------------------------------------
// Kernel 2: edge gather + scatter-add. One warp per edge; lane owns a float4.
// In-warp dtype detection (int64 vs int32-downcast edge_index).
// ---------------------------------------------------------------------------
__global__ __launch_bounds__(256)
void edge_scatter_kernel(const void* __restrict__ ei_raw,
                         float* __restrict__ out) {
    const int edge = (blockIdx.x * blockDim.x + threadIdx.x) >> 5;
    const int lane = threadIdx.x & 31;
    if (edge >= N_EDGES) return;

    const long long* ei64 = (const long long*)ei_raw;
    bool ok = true;
    if (lane < 8) {
        long long v = ei64[lane];
        ok = (v >= 0 && v < N_NODES);
    }
    const bool is64 = __all_sync(0xffffffffu, ok);

    long long row, col;
    if (is64) {
        row = ei64[edge];
        col = ei64[N_EDGES + edge];
    } else {
        const int* ei32 = (const int*)ei_raw;
        row = ei32[edge];
        col = ei32[N_EDGES + edge];
    }
    if (row < 0 || row >= N_NODES || col < 0 || col >= N_NODES) return;

    const float4* __restrict__ src =
        reinterpret_cast<const float4*>(g_h + (size_t)col * D);
    float4 v = src[lane];

    float* dst = out + (size_t)row * D + (size_t)lane * 4;
    asm volatile("red.global.add.v4.f32 [%0], {%1, %2, %3, %4};"
                 :: "l"(dst), "f"(v.x), "f"(v.y), "f"(v.z), "f"(v.w)
                 : "memory");
}

// ---------------------------------------------------------------------------
extern "C" void kernel_launch(void* const* d_in, const int* in_sizes, int n_in,
                              void* d_out, int out_size) {
    const float* x = nullptr; const void* ei = nullptr;
    const float* W = nullptr; const float* b = nullptr;
    for (int i = 0; i < n_in; i++) {
        switch (in_sizes[i]) {
            case N_NODES * D: x  = (const float*)d_in[i]; break;
            case 2 * N_EDGES: ei = d_in[i];               break;
            case D * D:       W  = (const float*)d_in[i]; break;
            case D:           b  = (const float*)d_in[i]; break;
        }
    }
    float* out = (float*)d_out;

    cudaFuncSetAttribute(gemm_tc_kernel,
                         cudaFuncAttributeMaxDynamicSharedMemorySize, SM_TOTAL);

    const int gemm_blocks = (N_NODES + 127) / 128;  // 391
    gemm_tc_kernel<<<gemm_blocks, 256, SM_TOTAL>>>(x, W, b, out);

    const int edges_per_block = 256 / 32;
    const int scatter_blocks = (N_EDGES + edges_per_block - 1) / edges_per_block;
    edge_scatter_kernel<<<scatter_blocks, 256>>>(ei, out);
}